// round 7
// baseline (speedup 1.0000x reference)
#include <cuda_runtime.h>
#include <cuda_bf16.h>
#include <cuda_fp16.h>
#include <cstdint>
#include <cstddef>

#define DIN  4096
#define DOUT 4096
#define RNK  8
#define MTOT 8192            // 4*2048 rows of x

// ------------------------- scratch (__device__ globals) -------------------------
__device__ float g_un[RNK * DIN];          // normalized Householder vectors, [r][DIN]
__device__ float g_T[RNK * RNK];           // compact-WY T (8x8)
__device__ __half g_wf[(size_t)DOUT * DIN];   // fp16 new W
__device__ __half g_xf[(size_t)MTOT * DIN];   // fp16 x

// ------------------------- PTX helpers (family-safe: sm_80-era) -------------------------
__device__ __forceinline__ uint32_t smem_u32(const void* p) {
    uint32_t a;
    asm("{ .reg .u64 t; cvta.to.shared.u64 t, %1; cvt.u32.u64 %0, t; }" : "=r"(a) : "l"(p));
    return a;
}

__device__ __forceinline__ void cp_async16(uint32_t saddr, const void* gptr) {
    asm volatile("cp.async.cg.shared.global [%0], [%1], 16;" :: "r"(saddr), "l"(gptr));
}
#define CP_COMMIT() asm volatile("cp.async.commit_group;" ::: "memory")
#define CP_WAIT2()  asm volatile("cp.async.wait_group 2;" ::: "memory")

#define LDMATRIX_X4(r0, r1, r2, r3, addr) \
    asm volatile("ldmatrix.sync.aligned.m8n8.x4.shared.b16 {%0,%1,%2,%3}, [%4];" \
                 : "=r"(r0), "=r"(r1), "=r"(r2), "=r"(r3) : "r"(addr))

#define MMA16816F16(d0, d1, d2, d3, a0, a1, a2, a3, b0, b1) \
    asm volatile("mma.sync.aligned.m16n8k16.row.col.f32.f16.f16.f32 " \
                 "{%0,%1,%2,%3}, {%4,%5,%6,%7}, {%8,%9}, {%0,%1,%2,%3};" \
                 : "+f"(d0), "+f"(d1), "+f"(d2), "+f"(d3) \
                 : "r"(a0), "r"(a1), "r"(a2), "r"(a3), "r"(b0), "r"(b1))

// ------------------------- K1: normalize u, Gram, build T -------------------------
__global__ void k_prep(const float* __restrict__ hra) {
    __shared__ float sR[64];
    __shared__ float sInv[8];
    int tid = threadIdx.x;
    if (tid < 64) sR[tid] = 0.f;
    __syncthreads();

    float acc[8][8];
#pragma unroll
    for (int i = 0; i < 8; i++)
#pragma unroll
        for (int j = 0; j < 8; j++) acc[i][j] = 0.f;

    for (int k = tid; k < DIN; k += 256) {
        float v[8];
#pragma unroll
        for (int i = 0; i < 8; i++) v[i] = hra[k * 8 + i];
#pragma unroll
        for (int i = 0; i < 8; i++)
#pragma unroll
            for (int j = 0; j < 8; j++) acc[i][j] += v[i] * v[j];
    }
#pragma unroll
    for (int i = 0; i < 8; i++)
#pragma unroll
        for (int j = 0; j < 8; j++) atomicAdd(&sR[i * 8 + j], acc[i][j]);
    __syncthreads();

    if (tid < 8) sInv[tid] = 1.0f / sqrtf(sR[tid * 8 + tid]);
    __syncthreads();

    for (int k = tid; k < DIN; k += 256) {
#pragma unroll
        for (int i = 0; i < 8; i++) g_un[i * DIN + k] = hra[k * 8 + i] * sInv[i];
    }

    if (tid == 0) {
        float G[8][8], T[8][8];
        for (int i = 0; i < 8; i++)
            for (int j = 0; j < 8; j++) G[i][j] = sR[i * 8 + j] * sInv[i] * sInv[j];
        for (int i = 0; i < 8; i++)
            for (int j = 0; j < 8; j++) T[i][j] = (i == j) ? 2.f : 0.f;
        for (int j = 1; j < 8; j++)
            for (int i = 0; i < j; i++) {
                float s = 0.f;
                for (int l = i; l < j; l++) s += T[i][l] * G[l][j];
                T[i][j] = -2.f * s;
            }
        for (int i = 0; i < 8; i++)
            for (int j = 0; j < 8; j++) g_T[i * 8 + j] = T[i][j];
    }
}

// ------------------------- K2: fused per-row W prep -------------------------
// For row n: p = (W[n,:] U) T; new_W[n,:] = W[n,:] - p u^T; write fp16.
// W row held in registers across both phases (single gmem read of W).
__global__ void k_wprep(const float* __restrict__ w) {
    const int n = blockIdx.x;
    const int tid = threadIdx.x;
    __shared__ float sAcc[8];
    __shared__ float sP[8];
    if (tid < 8) sAcc[tid] = 0.f;
    __syncthreads();

    const float4* wr = (const float4*)(w + (size_t)n * DIN);
    float4 rw[4];
#pragma unroll
    for (int q = 0; q < 4; q++) rw[q] = wr[tid + q * 256];

    float part[8] = {0, 0, 0, 0, 0, 0, 0, 0};
#pragma unroll
    for (int q = 0; q < 4; q++) {
        const int c4 = tid + q * 256;
#pragma unroll
        for (int i = 0; i < 8; i++) {
            const float4 u4 = *(const float4*)(g_un + i * DIN + c4 * 4);
            part[i] += rw[q].x * u4.x + rw[q].y * u4.y + rw[q].z * u4.z + rw[q].w * u4.w;
        }
    }
#pragma unroll
    for (int i = 0; i < 8; i++) {
        float v = part[i];
        v += __shfl_down_sync(0xFFFFFFFFu, v, 16);
        v += __shfl_down_sync(0xFFFFFFFFu, v, 8);
        v += __shfl_down_sync(0xFFFFFFFFu, v, 4);
        v += __shfl_down_sync(0xFFFFFFFFu, v, 2);
        v += __shfl_down_sync(0xFFFFFFFFu, v, 1);
        if ((tid & 31) == 0) atomicAdd(&sAcc[i], v);
    }
    __syncthreads();
    if (tid < 8) {
        float p = 0.f;
#pragma unroll
        for (int i = 0; i < 8; i++) p += sAcc[i] * g_T[i * 8 + tid];
        sP[tid] = p;
    }
    __syncthreads();

    uint2* wo = (uint2*)g_wf + (size_t)n * (DIN / 4);
#pragma unroll
    for (int q = 0; q < 4; q++) {
        const int c4 = tid + q * 256;
        float cx = 0.f, cy = 0.f, cz = 0.f, cw = 0.f;
#pragma unroll
        for (int j = 0; j < 8; j++) {
            const float4 u4 = *(const float4*)(g_un + j * DIN + c4 * 4);
            const float pj = sP[j];
            cx += pj * u4.x; cy += pj * u4.y; cz += pj * u4.z; cw += pj * u4.w;
        }
        __half2 h0 = __floats2half2_rn(rw[q].x - cx, rw[q].y - cy);
        __half2 h1 = __floats2half2_rn(rw[q].z - cz, rw[q].w - cw);
        uint2 o;
        o.x = *(uint32_t*)&h0;
        o.y = *(uint32_t*)&h1;
        wo[c4] = o;
    }
}

// ------------------------- K3: convert x to fp16 -------------------------
__global__ void k_xconv(const float* __restrict__ x) {
    size_t idx = (size_t)blockIdx.x * blockDim.x + threadIdx.x;
    size_t stride = (size_t)gridDim.x * blockDim.x;
    const float4* x4 = (const float4*)x;
    uint2* xo = (uint2*)g_xf;
    const size_t n4 = (size_t)MTOT * DIN / 4;
    for (size_t i = idx; i < n4; i += stride) {
        float4 v = x4[i];
        __half2 h0 = __floats2half2_rn(v.x, v.y);
        __half2 h1 = __floats2half2_rn(v.z, v.w);
        uint2 o;
        o.x = *(uint32_t*)&h0;
        o.y = *(uint32_t*)&h1;
        xo[i] = o;
    }
}

// ------------------------- K4: main GEMM via mma.sync fp16 -------------------------
// out[8192,4096] = Xf @ Wf^T, fp32 accumulate.
// CTA tile 128x256, K chunk 64, 4-stage cp.async pipeline.
// 512 threads / 16 warps (4 per SMSP): 2 over M x 8 over N; warp tile 64x32.
#define BK 64
#define NCHUNK (DIN / BK)              // 64
#define A_BYTES 16384                  // 128 rows x 128 B
#define B_BYTES 32768                  // 256 rows x 128 B
#define STAGE_BYTES (A_BYTES + B_BYTES)   // 48 KB
#define NSTAGE 4
#define GEMM_SMEM (NSTAGE * STAGE_BYTES)  // 196608

// SMEM layout per array: rows x 128B; 16B segments XOR-swizzled:
// phys(row, seg) = row*128 + ((seg ^ (row&7)) << 4)
__device__ __forceinline__ uint32_t swz(uint32_t row, uint32_t seg) {
    return row * 128u + (((seg ^ (row & 7u)) & 7u) << 4);
}

// 512 threads: each pass covers 64 rows (tid>>3) x 8 segs (tid&7).
__device__ __forceinline__ void load_A_part(int c, int st, int p, int m0,
                                            uint32_t sb, int tid) {
    const uint32_t sp = sb + st * STAGE_BYTES;
    const uint32_t seg = (uint32_t)(tid & 7);
    uint32_t row = (uint32_t)(tid >> 3) + p * 64u;
    const void* g = g_xf + (size_t)(m0 + (int)row) * DIN + c * BK + (int)seg * 8;
    cp_async16(sp + swz(row, seg), g);
}

__device__ __forceinline__ void load_B_part(int c, int st, int p, int n0,
                                            uint32_t sb, int tid) {
    const uint32_t sp = sb + st * STAGE_BYTES + A_BYTES;
    const uint32_t seg = (uint32_t)(tid & 7);
    uint32_t row = (uint32_t)(tid >> 3) + p * 64u;
    const void* g = g_wf + (size_t)(n0 + (int)row) * DIN + c * BK + (int)seg * 8;
    cp_async16(sp + swz(row, seg), g);
}

__device__ __forceinline__ void load_chunk(int c, int st, int m0, int n0,
                                           uint32_t sb, int tid) {
#pragma unroll
    for (int p = 0; p < 2; p++) load_A_part(c, st, p, m0, sb, tid);
#pragma unroll
    for (int p = 0; p < 4; p++) load_B_part(c, st, p, n0, sb, tid);
}

__global__ void __launch_bounds__(512, 1) k_gemm(float* __restrict__ out) {
    extern __shared__ char smem[];
    uint32_t sb = smem_u32(smem);
    const int tid = threadIdx.x;
    const int wid = tid >> 5;
    const int lane = tid & 31;

    // 64 m-tiles x 16 n-tiles
    const int tn = blockIdx.x & 15;
    const int tm = blockIdx.x >> 4;
    const int m0 = tm << 7;
    const int n0 = tn << 8;

    const int warp_m = wid & 1;        // 2 warps over M (64 rows each)
    const int warp_n = wid >> 1;       // 8 warps over N (32 cols each)

    const uint32_t lr  = (uint32_t)(lane & 7);
    const uint32_t q8  = (uint32_t)((lane >> 3) & 1);   // +8 rows
    const uint32_t sk  = (uint32_t)((lane >> 4) & 1);   // 16B half within k16

    // Per-lane precomputed row terms for A (4 m16 tiles) and B (2 n16 groups)
    uint32_t a_rt[4], a_sw[4], b_rt[2], b_sw[2];
#pragma unroll
    for (int i = 0; i < 4; i++) {
        uint32_t row = (uint32_t)(warp_m * 64 + i * 16) + lr + q8 * 8;
        a_rt[i] = row * 128u;
        a_sw[i] = row & 7u;
    }
#pragma unroll
    for (int j = 0; j < 2; j++) {
        uint32_t row = (uint32_t)(warp_n * 32 + j * 16) + lr + q8 * 8;
        b_rt[j] = row * 128u;
        b_sw[j] = row & 7u;
    }

    float acc[4][4][4];
#pragma unroll
    for (int i = 0; i < 4; i++)
#pragma unroll
        for (int j = 0; j < 4; j++)
#pragma unroll
            for (int r = 0; r < 4; r++) acc[i][j][r] = 0.f;

    // prologue: fill 3 stages
    load_chunk(0, 0, m0, n0, sb, tid); CP_COMMIT();
    load_chunk(1, 1, m0, n0, sb, tid); CP_COMMIT();
    load_chunk(2, 2, m0, n0, sb, tid); CP_COMMIT();

    for (int c = 0; c < NCHUNK; ++c) {
        const int st = c & 3;
        const int pf = c + 3;                 // chunk to prefetch
        const int pst = pf & 3;
        const bool do_pf = (pf < NCHUNK);

        CP_WAIT2();
        __syncthreads();

        const uint32_t sA = sb + st * STAGE_BYTES;
        const uint32_t sB = sA + A_BYTES;

#pragma unroll
        for (int s = 0; s < 4; ++s) {
            const uint32_t seg = 2u * (uint32_t)s + sk;

            uint32_t a[4][4], b[4][2];
#pragma unroll
            for (int i = 0; i < 4; i++) {
                uint32_t off = a_rt[i] + (((seg ^ a_sw[i]) & 7u) << 4);
                LDMATRIX_X4(a[i][0], a[i][1], a[i][2], a[i][3], sA + off);
            }
#pragma unroll
            for (int j = 0; j < 2; j++) {
                uint32_t off = b_rt[j] + (((seg ^ b_sw[j]) & 7u) << 4);
                uint32_t r0, r1, r2, r3;
                LDMATRIX_X4(r0, r1, r2, r3, sB + off);
                b[2 * j][0] = r0; b[2 * j][1] = r2;
                b[2 * j + 1][0] = r1; b[2 * j + 1][1] = r3;
            }

            // interleave prefetch: 6 passes spread over 4 k-steps
            if (do_pf) {
                if (s == 0) { load_A_part(pf, pst, 0, m0, sb, tid);
                              load_B_part(pf, pst, 0, n0, sb, tid); }
                if (s == 1) { load_A_part(pf, pst, 1, m0, sb, tid);
                              load_B_part(pf, pst, 1, n0, sb, tid); }
                if (s == 2)   load_B_part(pf, pst, 2, n0, sb, tid);
                if (s == 3)   load_B_part(pf, pst, 3, n0, sb, tid);
            }

#pragma unroll
            for (int i = 0; i < 4; i++) {
#pragma unroll
                for (int j = 0; j < 4; j++) {
                    MMA16816F16(acc[i][j][0], acc[i][j][1], acc[i][j][2], acc[i][j][3],
                                a[i][0], a[i][1], a[i][2], a[i][3],
                                b[j][0], b[j][1]);
                }
            }
        }
        CP_COMMIT();   // one group per chunk (possibly empty near the tail)
    }

    // epilogue: direct fp32 stores (thread owns rows m, m+8; cols 2*(lane&3)+{0,1})
    const int rbase = m0 + warp_m * 64 + (lane >> 2);
    const int cbase = n0 + warp_n * 32 + (lane & 3) * 2;
#pragma unroll
    for (int i = 0; i < 4; i++) {
#pragma unroll
        for (int j = 0; j < 4; j++) {
            float2 v0 = make_float2(acc[i][j][0], acc[i][j][1]);
            float2 v1 = make_float2(acc[i][j][2], acc[i][j][3]);
            size_t r0 = (size_t)(rbase + i * 16) * DOUT + (cbase + j * 8);
            size_t r1 = r0 + 8 * (size_t)DOUT;
            *(float2*)(out + r0) = v0;
            *(float2*)(out + r1) = v1;
        }
    }
}

// ------------------------- launch -------------------------
extern "C" void kernel_launch(void* const* d_in, const int* in_sizes, int n_in,
                              void* d_out, int out_size) {
    (void)in_sizes; (void)n_in; (void)out_size;
    const float* x   = (const float*)d_in[0];
    const float* w   = (const float*)d_in[1];
    const float* hra = (const float*)d_in[2];
    float* out = (float*)d_out;

    k_prep<<<1, 256>>>(hra);
    k_wprep<<<DOUT, 256>>>(w);
    k_xconv<<<8192, 256>>>(x);

    cudaFuncSetAttribute(k_gemm, cudaFuncAttributeMaxDynamicSharedMemorySize, GEMM_SMEM);
    k_gemm<<<(MTOT / 128) * (DOUT / 256), 512, GEMM_SMEM>>>(out);
}

// round 10
// speedup vs baseline: 1.0324x; 1.0324x over previous
#include <cuda_runtime.h>
#include <cuda_bf16.h>
#include <cuda_fp16.h>
#include <cstdint>
#include <cstddef>

#define DIN  4096
#define DOUT 4096
#define RNK  8
#define MTOT 8192            // 4*2048 rows of x

// ------------------------- scratch (__device__ globals) -------------------------
__device__ float g_un[RNK * DIN];          // normalized Householder vectors, [r][DIN]
__device__ float g_T[RNK * RNK];           // compact-WY T (8x8)
__device__ __half g_wf[(size_t)DOUT * DIN];   // fp16 new W
__device__ __half g_xf[(size_t)MTOT * DIN];   // fp16 x

// ------------------------- PTX helpers (family-safe: sm_80-era) -------------------------
__device__ __forceinline__ uint32_t smem_u32(const void* p) {
    uint32_t a;
    asm("{ .reg .u64 t; cvta.to.shared.u64 t, %1; cvt.u32.u64 %0, t; }" : "=r"(a) : "l"(p));
    return a;
}

__device__ __forceinline__ void cp_async16(uint32_t saddr, const void* gptr) {
    asm volatile("cp.async.cg.shared.global [%0], [%1], 16;" :: "r"(saddr), "l"(gptr));
}
#define CP_COMMIT() asm volatile("cp.async.commit_group;" ::: "memory")
#define CP_WAIT1()  asm volatile("cp.async.wait_group 1;" ::: "memory")

#define LDMATRIX_X4(r0, r1, r2, r3, addr) \
    asm volatile("ldmatrix.sync.aligned.m8n8.x4.shared.b16 {%0,%1,%2,%3}, [%4];" \
                 : "=r"(r0), "=r"(r1), "=r"(r2), "=r"(r3) : "r"(addr))

#define MMA16816F16(d0, d1, d2, d3, a0, a1, a2, a3, b0, b1) \
    asm volatile("mma.sync.aligned.m16n8k16.row.col.f32.f16.f16.f32 " \
                 "{%0,%1,%2,%3}, {%4,%5,%6,%7}, {%8,%9}, {%0,%1,%2,%3};" \
                 : "+f"(d0), "+f"(d1), "+f"(d2), "+f"(d3) \
                 : "r"(a0), "r"(a1), "r"(a2), "r"(a3), "r"(b0), "r"(b1))

// ------------------------- K1: normalize u, Gram, build T -------------------------
__global__ void k_prep(const float* __restrict__ hra) {
    __shared__ float sR[64];
    __shared__ float sInv[8];
    int tid = threadIdx.x;
    if (tid < 64) sR[tid] = 0.f;
    __syncthreads();

    float acc[8][8];
#pragma unroll
    for (int i = 0; i < 8; i++)
#pragma unroll
        for (int j = 0; j < 8; j++) acc[i][j] = 0.f;

    for (int k = tid; k < DIN; k += 256) {
        float v[8];
#pragma unroll
        for (int i = 0; i < 8; i++) v[i] = hra[k * 8 + i];
#pragma unroll
        for (int i = 0; i < 8; i++)
#pragma unroll
            for (int j = 0; j < 8; j++) acc[i][j] += v[i] * v[j];
    }
#pragma unroll
    for (int i = 0; i < 8; i++)
#pragma unroll
        for (int j = 0; j < 8; j++) atomicAdd(&sR[i * 8 + j], acc[i][j]);
    __syncthreads();

    if (tid < 8) sInv[tid] = 1.0f / sqrtf(sR[tid * 8 + tid]);
    __syncthreads();

    for (int k = tid; k < DIN; k += 256) {
#pragma unroll
        for (int i = 0; i < 8; i++) g_un[i * DIN + k] = hra[k * 8 + i] * sInv[i];
    }

    if (tid == 0) {
        float G[8][8], T[8][8];
        for (int i = 0; i < 8; i++)
            for (int j = 0; j < 8; j++) G[i][j] = sR[i * 8 + j] * sInv[i] * sInv[j];
        for (int i = 0; i < 8; i++)
            for (int j = 0; j < 8; j++) T[i][j] = (i == j) ? 2.f : 0.f;
        for (int j = 1; j < 8; j++)
            for (int i = 0; i < j; i++) {
                float s = 0.f;
                for (int l = i; l < j; l++) s += T[i][l] * G[l][j];
                T[i][j] = -2.f * s;
            }
        for (int i = 0; i < 8; i++)
            for (int j = 0; j < 8; j++) g_T[i * 8 + j] = T[i][j];
    }
}

// ------------------------- K2: fused per-row W prep -------------------------
__global__ void k_wprep(const float* __restrict__ w) {
    const int n = blockIdx.x;
    const int tid = threadIdx.x;
    __shared__ float sAcc[8];
    __shared__ float sP[8];
    if (tid < 8) sAcc[tid] = 0.f;
    __syncthreads();

    const float4* wr = (const float4*)(w + (size_t)n * DIN);
    float4 rw[4];
#pragma unroll
    for (int q = 0; q < 4; q++) rw[q] = wr[tid + q * 256];

    float part[8] = {0, 0, 0, 0, 0, 0, 0, 0};
#pragma unroll
    for (int q = 0; q < 4; q++) {
        const int c4 = tid + q * 256;
#pragma unroll
        for (int i = 0; i < 8; i++) {
            const float4 u4 = *(const float4*)(g_un + i * DIN + c4 * 4);
            part[i] += rw[q].x * u4.x + rw[q].y * u4.y + rw[q].z * u4.z + rw[q].w * u4.w;
        }
    }
#pragma unroll
    for (int i = 0; i < 8; i++) {
        float v = part[i];
        v += __shfl_down_sync(0xFFFFFFFFu, v, 16);
        v += __shfl_down_sync(0xFFFFFFFFu, v, 8);
        v += __shfl_down_sync(0xFFFFFFFFu, v, 4);
        v += __shfl_down_sync(0xFFFFFFFFu, v, 2);
        v += __shfl_down_sync(0xFFFFFFFFu, v, 1);
        if ((tid & 31) == 0) atomicAdd(&sAcc[i], v);
    }
    __syncthreads();
    if (tid < 8) {
        float p = 0.f;
#pragma unroll
        for (int i = 0; i < 8; i++) p += sAcc[i] * g_T[i * 8 + tid];
        sP[tid] = p;
    }
    __syncthreads();

    uint2* wo = (uint2*)g_wf + (size_t)n * (DIN / 4);
#pragma unroll
    for (int q = 0; q < 4; q++) {
        const int c4 = tid + q * 256;
        float cx = 0.f, cy = 0.f, cz = 0.f, cw = 0.f;
#pragma unroll
        for (int j = 0; j < 8; j++) {
            const float4 u4 = *(const float4*)(g_un + j * DIN + c4 * 4);
            const float pj = sP[j];
            cx += pj * u4.x; cy += pj * u4.y; cz += pj * u4.z; cw += pj * u4.w;
        }
        __half2 h0 = __floats2half2_rn(rw[q].x - cx, rw[q].y - cy);
        __half2 h1 = __floats2half2_rn(rw[q].z - cz, rw[q].w - cw);
        uint2 o;
        o.x = *(uint32_t*)&h0;
        o.y = *(uint32_t*)&h1;
        wo[c4] = o;
    }
}

// ------------------------- K3: convert x to fp16 -------------------------
__global__ void k_xconv(const float* __restrict__ x) {
    size_t idx = (size_t)blockIdx.x * blockDim.x + threadIdx.x;
    size_t stride = (size_t)gridDim.x * blockDim.x;
    const float4* x4 = (const float4*)x;
    uint2* xo = (uint2*)g_xf;
    const size_t n4 = (size_t)MTOT * DIN / 4;
    for (size_t i = idx; i < n4; i += stride) {
        float4 v = x4[i];
        __half2 h0 = __floats2half2_rn(v.x, v.y);
        __half2 h1 = __floats2half2_rn(v.z, v.w);
        uint2 o;
        o.x = *(uint32_t*)&h0;
        o.y = *(uint32_t*)&h1;
        xo[i] = o;
    }
}

// ------------------------- K4: main GEMM via mma.sync fp16 -------------------------
// out[8192,4096] = Xf @ Wf^T, fp32 accumulate.
// CTA tile 128x128, K chunk 64, 3-stage cp.async pipeline, 96 KB SMEM -> 2 CTAs/SM.
// 8 warps: 2 over M x 4 over N; warp tile 64x32.
#define BK 64
#define NCHUNK (DIN / BK)              // 64
#define A_BYTES 16384                  // 128 rows x 128 B
#define B_BYTES 16384                  // 128 rows x 128 B
#define STAGE_BYTES (A_BYTES + B_BYTES)   // 32 KB
#define NSTAGE 3
#define GEMM_SMEM (NSTAGE * STAGE_BYTES)  // 98304

// SMEM layout per array: rows x 128B; 16B segments XOR-swizzled:
// phys(row, seg) = row*128 + ((seg ^ (row&7)) << 4)
__device__ __forceinline__ uint32_t swz(uint32_t row, uint32_t seg) {
    return row * 128u + (((seg ^ (row & 7u)) & 7u) << 4);
}

// 256 threads: one pass covers 32 rows (tid>>3) x 8 segs (tid&7).
__device__ __forceinline__ void load_A_part(int c, int st, int p, int m0,
                                            uint32_t sb, int tid) {
    const uint32_t sp = sb + st * STAGE_BYTES;
    const uint32_t seg = (uint32_t)(tid & 7);
    uint32_t row = (uint32_t)(tid >> 3) + p * 32u;
    const void* g = g_xf + (size_t)(m0 + (int)row) * DIN + c * BK + (int)seg * 8;
    cp_async16(sp + swz(row, seg), g);
}

__device__ __forceinline__ void load_B_part(int c, int st, int p, int n0,
                                            uint32_t sb, int tid) {
    const uint32_t sp = sb + st * STAGE_BYTES + A_BYTES;
    const uint32_t seg = (uint32_t)(tid & 7);
    uint32_t row = (uint32_t)(tid >> 3) + p * 32u;
    const void* g = g_wf + (size_t)(n0 + (int)row) * DIN + c * BK + (int)seg * 8;
    cp_async16(sp + swz(row, seg), g);
}

__device__ __forceinline__ void load_chunk(int c, int st, int m0, int n0,
                                           uint32_t sb, int tid) {
#pragma unroll
    for (int p = 0; p < 4; p++) load_A_part(c, st, p, m0, sb, tid);
#pragma unroll
    for (int p = 0; p < 4; p++) load_B_part(c, st, p, n0, sb, tid);
}

__global__ void __launch_bounds__(256, 2) k_gemm(float* __restrict__ out) {
    extern __shared__ char smem[];
    uint32_t sb = smem_u32(smem);
    const int tid = threadIdx.x;
    const int wid = tid >> 5;
    const int lane = tid & 31;

    // 64 m-tiles x 32 n-tiles
    const int tn = blockIdx.x & 31;
    const int tm = blockIdx.x >> 5;
    const int m0 = tm << 7;
    const int n0 = tn << 7;

    const int warp_m = wid & 1;        // 2 warps over M (64 rows each)
    const int warp_n = wid >> 1;       // 4 warps over N (32 cols each)

    const uint32_t lr  = (uint32_t)(lane & 7);
    const uint32_t q8  = (uint32_t)((lane >> 3) & 1);   // +8 rows
    const uint32_t sk  = (uint32_t)((lane >> 4) & 1);   // 16B half within k16

    // Per-lane precomputed row terms for A (4 m16 tiles) and B (2 n16 groups)
    uint32_t a_rt[4], a_sw[4], b_rt[2], b_sw[2];
#pragma unroll
    for (int i = 0; i < 4; i++) {
        uint32_t row = (uint32_t)(warp_m * 64 + i * 16) + lr + q8 * 8;
        a_rt[i] = row * 128u;
        a_sw[i] = row & 7u;
    }
#pragma unroll
    for (int j = 0; j < 2; j++) {
        uint32_t row = (uint32_t)(warp_n * 32 + j * 16) + lr + q8 * 8;
        b_rt[j] = row * 128u;
        b_sw[j] = row & 7u;
    }

    float acc[4][4][4];
#pragma unroll
    for (int i = 0; i < 4; i++)
#pragma unroll
        for (int j = 0; j < 4; j++)
#pragma unroll
            for (int r = 0; r < 4; r++) acc[i][j][r] = 0.f;

    // prologue: fill 2 stages
    load_chunk(0, 0, m0, n0, sb, tid); CP_COMMIT();
    load_chunk(1, 1, m0, n0, sb, tid); CP_COMMIT();

    for (int c = 0; c < NCHUNK; ++c) {
        const int st = c % 3;
        const int pf = c + 2;                 // chunk to prefetch
        const int pst = pf % 3;
        const bool do_pf = (pf < NCHUNK);

        CP_WAIT1();
        __syncthreads();

        const uint32_t sA = sb + st * STAGE_BYTES;
        const uint32_t sB = sA + A_BYTES;

#pragma unroll
        for (int s = 0; s < 4; ++s) {
            const uint32_t seg = 2u * (uint32_t)s + sk;

            uint32_t a[4][4], b[4][2];
#pragma unroll
            for (int i = 0; i < 4; i++) {
                uint32_t off = a_rt[i] + (((seg ^ a_sw[i]) & 7u) << 4);
                LDMATRIX_X4(a[i][0], a[i][1], a[i][2], a[i][3], sA + off);
            }
#pragma unroll
            for (int j = 0; j < 2; j++) {
                uint32_t off = b_rt[j] + (((seg ^ b_sw[j]) & 7u) << 4);
                uint32_t r0, r1, r2, r3;
                LDMATRIX_X4(r0, r1, r2, r3, sB + off);
                b[2 * j][0] = r0; b[2 * j][1] = r2;
                b[2 * j + 1][0] = r1; b[2 * j + 1][1] = r3;
            }

            // interleave prefetch: 8 passes spread over 4 k-steps
            if (do_pf) {
                load_A_part(pf, pst, s, m0, sb, tid);
                load_B_part(pf, pst, s, n0, sb, tid);
            }

#pragma unroll
            for (int i = 0; i < 4; i++) {
#pragma unroll
                for (int j = 0; j < 4; j++) {
                    MMA16816F16(acc[i][j][0], acc[i][j][1], acc[i][j][2], acc[i][j][3],
                                a[i][0], a[i][1], a[i][2], a[i][3],
                                b[j][0], b[j][1]);
                }
            }
        }
        CP_COMMIT();   // one group per chunk (possibly empty near the tail)
    }

    // epilogue: direct fp32 stores (thread owns rows m, m+8; cols 2*(lane&3)+{0,1})
    const int rbase = m0 + warp_m * 64 + (lane >> 2);
    const int cbase = n0 + warp_n * 32 + (lane & 3) * 2;
#pragma unroll
    for (int i = 0; i < 4; i++) {
#pragma unroll
        for (int j = 0; j < 4; j++) {
            float2 v0 = make_float2(acc[i][j][0], acc[i][j][1]);
            float2 v1 = make_float2(acc[i][j][2], acc[i][j][3]);
            size_t r0 = (size_t)(rbase + i * 16) * DOUT + (cbase + j * 8);
            size_t r1 = r0 + 8 * (size_t)DOUT;
            *(float2*)(out + r0) = v0;
            *(float2*)(out + r1) = v1;
        }
    }
}

// ------------------------- launch -------------------------
extern "C" void kernel_launch(void* const* d_in, const int* in_sizes, int n_in,
                              void* d_out, int out_size) {
    (void)in_sizes; (void)n_in; (void)out_size;
    const float* x   = (const float*)d_in[0];
    const float* w   = (const float*)d_in[1];
    const float* hra = (const float*)d_in[2];
    float* out = (float*)d_out;

    k_prep<<<1, 256>>>(hra);
    k_wprep<<<DOUT, 256>>>(w);
    k_xconv<<<8192, 256>>>(x);

    cudaFuncSetAttribute(k_gemm, cudaFuncAttributeMaxDynamicSharedMemorySize, GEMM_SMEM);
    k_gemm<<<(MTOT / 128) * (DOUT / 128), 256, GEMM_SMEM>>>(out);
}

// round 11
// speedup vs baseline: 1.0581x; 1.0249x over previous
#include <cuda_runtime.h>
#include <cuda_bf16.h>
#include <cuda_fp16.h>
#include <cstdint>
#include <cstddef>

#define DIN  4096
#define DOUT 4096
#define RNK  8
#define MTOT 8192            // 4*2048 rows of x

// ------------------------- scratch (__device__ globals) -------------------------
__device__ float g_un[RNK * DIN];          // normalized Householder vectors, [r][DIN]
__device__ float g_T[RNK * RNK];           // compact-WY T (8x8)
__device__ __half g_wf[(size_t)DOUT * DIN];   // fp16 new W
__device__ __half g_xf[(size_t)MTOT * DIN];   // fp16 x

// ------------------------- PTX helpers (family-safe: sm_80-era) -------------------------
__device__ __forceinline__ uint32_t smem_u32(const void* p) {
    uint32_t a;
    asm("{ .reg .u64 t; cvta.to.shared.u64 t, %1; cvt.u32.u64 %0, t; }" : "=r"(a) : "l"(p));
    return a;
}

__device__ __forceinline__ void cp_async16(uint32_t saddr, const void* gptr) {
    asm volatile("cp.async.cg.shared.global [%0], [%1], 16;" :: "r"(saddr), "l"(gptr));
}
#define CP_COMMIT() asm volatile("cp.async.commit_group;" ::: "memory")
#define CP_WAIT1()  asm volatile("cp.async.wait_group 1;" ::: "memory")

#define LDMATRIX_X4(r0, r1, r2, r3, addr) \
    asm volatile("ldmatrix.sync.aligned.m8n8.x4.shared.b16 {%0,%1,%2,%3}, [%4];" \
                 : "=r"(r0), "=r"(r1), "=r"(r2), "=r"(r3) : "r"(addr))

#define MMA16816F16(d0, d1, d2, d3, a0, a1, a2, a3, b0, b1) \
    asm volatile("mma.sync.aligned.m16n8k16.row.col.f32.f16.f16.f32 " \
                 "{%0,%1,%2,%3}, {%4,%5,%6,%7}, {%8,%9}, {%0,%1,%2,%3};" \
                 : "+f"(d0), "+f"(d1), "+f"(d2), "+f"(d3) \
                 : "r"(a0), "r"(a1), "r"(a2), "r"(a3), "r"(b0), "r"(b1))

// ------------------------- K1: normalize u, Gram, build T -------------------------
__global__ void k_prep(const float* __restrict__ hra) {
    __shared__ float sR[64];
    __shared__ float sInv[8];
    int tid = threadIdx.x;
    if (tid < 64) sR[tid] = 0.f;
    __syncthreads();

    float acc[8][8];
#pragma unroll
    for (int i = 0; i < 8; i++)
#pragma unroll
        for (int j = 0; j < 8; j++) acc[i][j] = 0.f;

    for (int k = tid; k < DIN; k += 256) {
        float v[8];
#pragma unroll
        for (int i = 0; i < 8; i++) v[i] = hra[k * 8 + i];
#pragma unroll
        for (int i = 0; i < 8; i++)
#pragma unroll
            for (int j = 0; j < 8; j++) acc[i][j] += v[i] * v[j];
    }
#pragma unroll
    for (int i = 0; i < 8; i++)
#pragma unroll
        for (int j = 0; j < 8; j++) atomicAdd(&sR[i * 8 + j], acc[i][j]);
    __syncthreads();

    if (tid < 8) sInv[tid] = 1.0f / sqrtf(sR[tid * 8 + tid]);
    __syncthreads();

    for (int k = tid; k < DIN; k += 256) {
#pragma unroll
        for (int i = 0; i < 8; i++) g_un[i * DIN + k] = hra[k * 8 + i] * sInv[i];
    }

    if (tid == 0) {
        float G[8][8], T[8][8];
        for (int i = 0; i < 8; i++)
            for (int j = 0; j < 8; j++) G[i][j] = sR[i * 8 + j] * sInv[i] * sInv[j];
        for (int i = 0; i < 8; i++)
            for (int j = 0; j < 8; j++) T[i][j] = (i == j) ? 2.f : 0.f;
        for (int j = 1; j < 8; j++)
            for (int i = 0; i < j; i++) {
                float s = 0.f;
                for (int l = i; l < j; l++) s += T[i][l] * G[l][j];
                T[i][j] = -2.f * s;
            }
        for (int i = 0; i < 8; i++)
            for (int j = 0; j < 8; j++) g_T[i * 8 + j] = T[i][j];
    }
}

// ------------------------- K2: fused per-row W prep -------------------------
__global__ void k_wprep(const float* __restrict__ w) {
    const int n = blockIdx.x;
    const int tid = threadIdx.x;
    __shared__ float sAcc[8];
    __shared__ float sP[8];
    if (tid < 8) sAcc[tid] = 0.f;
    __syncthreads();

    const float4* wr = (const float4*)(w + (size_t)n * DIN);
    float4 rw[4];
#pragma unroll
    for (int q = 0; q < 4; q++) rw[q] = wr[tid + q * 256];

    float part[8] = {0, 0, 0, 0, 0, 0, 0, 0};
#pragma unroll
    for (int q = 0; q < 4; q++) {
        const int c4 = tid + q * 256;
#pragma unroll
        for (int i = 0; i < 8; i++) {
            const float4 u4 = *(const float4*)(g_un + i * DIN + c4 * 4);
            part[i] += rw[q].x * u4.x + rw[q].y * u4.y + rw[q].z * u4.z + rw[q].w * u4.w;
        }
    }
#pragma unroll
    for (int i = 0; i < 8; i++) {
        float v = part[i];
        v += __shfl_down_sync(0xFFFFFFFFu, v, 16);
        v += __shfl_down_sync(0xFFFFFFFFu, v, 8);
        v += __shfl_down_sync(0xFFFFFFFFu, v, 4);
        v += __shfl_down_sync(0xFFFFFFFFu, v, 2);
        v += __shfl_down_sync(0xFFFFFFFFu, v, 1);
        if ((tid & 31) == 0) atomicAdd(&sAcc[i], v);
    }
    __syncthreads();
    if (tid < 8) {
        float p = 0.f;
#pragma unroll
        for (int i = 0; i < 8; i++) p += sAcc[i] * g_T[i * 8 + tid];
        sP[tid] = p;
    }
    __syncthreads();

    uint2* wo = (uint2*)g_wf + (size_t)n * (DIN / 4);
#pragma unroll
    for (int q = 0; q < 4; q++) {
        const int c4 = tid + q * 256;
        float cx = 0.f, cy = 0.f, cz = 0.f, cw = 0.f;
#pragma unroll
        for (int j = 0; j < 8; j++) {
            const float4 u4 = *(const float4*)(g_un + j * DIN + c4 * 4);
            const float pj = sP[j];
            cx += pj * u4.x; cy += pj * u4.y; cz += pj * u4.z; cw += pj * u4.w;
        }
        __half2 h0 = __floats2half2_rn(rw[q].x - cx, rw[q].y - cy);
        __half2 h1 = __floats2half2_rn(rw[q].z - cz, rw[q].w - cw);
        uint2 o;
        o.x = *(uint32_t*)&h0;
        o.y = *(uint32_t*)&h1;
        wo[c4] = o;
    }
}

// ------------------------- K3: convert x to fp16 -------------------------
__global__ void k_xconv(const float* __restrict__ x) {
    size_t idx = (size_t)blockIdx.x * blockDim.x + threadIdx.x;
    size_t stride = (size_t)gridDim.x * blockDim.x;
    const float4* x4 = (const float4*)x;
    uint2* xo = (uint2*)g_xf;
    const size_t n4 = (size_t)MTOT * DIN / 4;
    for (size_t i = idx; i < n4; i += stride) {
        float4 v = x4[i];
        __half2 h0 = __floats2half2_rn(v.x, v.y);
        __half2 h1 = __floats2half2_rn(v.z, v.w);
        uint2 o;
        o.x = *(uint32_t*)&h0;
        o.y = *(uint32_t*)&h1;
        xo[i] = o;
    }
}

// ------------------------- K4: main GEMM via mma.sync fp16 -------------------------
// out[8192,4096] = Xf @ Wf^T, fp32 accumulate.
// CTA tile 128x128, K chunk 64, 3-stage cp.async pipeline, 96 KB SMEM -> 2 CTAs/SM.
// 128 threads / 4 warps: 2 over M x 2 over N; warp tile 64x64 (0.25 LDSM per MMA).
#define BK 64
#define NCHUNK (DIN / BK)              // 64
#define A_BYTES 16384                  // 128 rows x 128 B
#define B_BYTES 16384                  // 128 rows x 128 B
#define STAGE_BYTES (A_BYTES + B_BYTES)   // 32 KB
#define NSTAGE 3
#define GEMM_SMEM (NSTAGE * STAGE_BYTES)  // 98304

// SMEM layout per array: rows x 128B; 16B segments XOR-swizzled:
// phys(row, seg) = row*128 + ((seg ^ (row&7)) << 4)
__device__ __forceinline__ uint32_t swz(uint32_t row, uint32_t seg) {
    return row * 128u + (((seg ^ (row & 7u)) & 7u) << 4);
}

// 128 threads: one pass covers 16 rows (tid>>3) x 8 segs (tid&7).
__device__ __forceinline__ void load_A_part(int c, int st, int p, int m0,
                                            uint32_t sb, int tid) {
    const uint32_t sp = sb + st * STAGE_BYTES;
    const uint32_t seg = (uint32_t)(tid & 7);
    uint32_t row = (uint32_t)(tid >> 3) + p * 16u;
    const void* g = g_xf + (size_t)(m0 + (int)row) * DIN + c * BK + (int)seg * 8;
    cp_async16(sp + swz(row, seg), g);
}

__device__ __forceinline__ void load_B_part(int c, int st, int p, int n0,
                                            uint32_t sb, int tid) {
    const uint32_t sp = sb + st * STAGE_BYTES + A_BYTES;
    const uint32_t seg = (uint32_t)(tid & 7);
    uint32_t row = (uint32_t)(tid >> 3) + p * 16u;
    const void* g = g_wf + (size_t)(n0 + (int)row) * DIN + c * BK + (int)seg * 8;
    cp_async16(sp + swz(row, seg), g);
}

__device__ __forceinline__ void load_chunk(int c, int st, int m0, int n0,
                                           uint32_t sb, int tid) {
#pragma unroll
    for (int p = 0; p < 8; p++) load_A_part(c, st, p, m0, sb, tid);
#pragma unroll
    for (int p = 0; p < 8; p++) load_B_part(c, st, p, n0, sb, tid);
}

__global__ void __launch_bounds__(128, 2) k_gemm(float* __restrict__ out) {
    extern __shared__ char smem[];
    uint32_t sb = smem_u32(smem);
    const int tid = threadIdx.x;
    const int wid = tid >> 5;
    const int lane = tid & 31;

    // 64 m-tiles x 32 n-tiles
    const int tn = blockIdx.x & 31;
    const int tm = blockIdx.x >> 5;
    const int m0 = tm << 7;
    const int n0 = tn << 7;

    const int warp_m = wid & 1;        // 2 warps over M (64 rows each)
    const int warp_n = wid >> 1;       // 2 warps over N (64 cols each)

    const uint32_t lr  = (uint32_t)(lane & 7);
    const uint32_t q8  = (uint32_t)((lane >> 3) & 1);   // +8 rows
    const uint32_t sk  = (uint32_t)((lane >> 4) & 1);   // 16B half within k16

    // Per-lane precomputed row terms for A (4 m16 tiles) and B (4 n16 groups)
    uint32_t a_rt[4], a_sw[4], b_rt[4], b_sw[4];
#pragma unroll
    for (int i = 0; i < 4; i++) {
        uint32_t row = (uint32_t)(warp_m * 64 + i * 16) + lr + q8 * 8;
        a_rt[i] = row * 128u;
        a_sw[i] = row & 7u;
    }
#pragma unroll
    for (int j = 0; j < 4; j++) {
        uint32_t row = (uint32_t)(warp_n * 64 + j * 16) + lr + q8 * 8;
        b_rt[j] = row * 128u;
        b_sw[j] = row & 7u;
    }

    float acc[4][8][4];
#pragma unroll
    for (int i = 0; i < 4; i++)
#pragma unroll
        for (int j = 0; j < 8; j++)
#pragma unroll
            for (int r = 0; r < 4; r++) acc[i][j][r] = 0.f;

    // prologue: fill 2 stages
    load_chunk(0, 0, m0, n0, sb, tid); CP_COMMIT();
    load_chunk(1, 1, m0, n0, sb, tid); CP_COMMIT();

    for (int c = 0; c < NCHUNK; ++c) {
        const int st = c % 3;
        const int pf = c + 2;                 // chunk to prefetch
        const int pst = pf % 3;
        const bool do_pf = (pf < NCHUNK);

        CP_WAIT1();
        __syncthreads();

        const uint32_t sA = sb + st * STAGE_BYTES;
        const uint32_t sB = sA + A_BYTES;

#pragma unroll
        for (int s = 0; s < 4; ++s) {
            const uint32_t seg = 2u * (uint32_t)s + sk;

            uint32_t a[4][4], b[8][2];
#pragma unroll
            for (int i = 0; i < 4; i++) {
                uint32_t off = a_rt[i] + (((seg ^ a_sw[i]) & 7u) << 4);
                LDMATRIX_X4(a[i][0], a[i][1], a[i][2], a[i][3], sA + off);
            }
#pragma unroll
            for (int j = 0; j < 4; j++) {
                uint32_t off = b_rt[j] + (((seg ^ b_sw[j]) & 7u) << 4);
                uint32_t r0, r1, r2, r3;
                LDMATRIX_X4(r0, r1, r2, r3, sB + off);
                b[2 * j][0] = r0; b[2 * j][1] = r2;
                b[2 * j + 1][0] = r1; b[2 * j + 1][1] = r3;
            }

            // interleave prefetch: 16 passes spread over 4 k-steps
            if (do_pf) {
                load_A_part(pf, pst, 2 * s, m0, sb, tid);
                load_A_part(pf, pst, 2 * s + 1, m0, sb, tid);
                load_B_part(pf, pst, 2 * s, n0, sb, tid);
                load_B_part(pf, pst, 2 * s + 1, n0, sb, tid);
            }

#pragma unroll
            for (int i = 0; i < 4; i++) {
#pragma unroll
                for (int j = 0; j < 8; j++) {
                    MMA16816F16(acc[i][j][0], acc[i][j][1], acc[i][j][2], acc[i][j][3],
                                a[i][0], a[i][1], a[i][2], a[i][3],
                                b[j][0], b[j][1]);
                }
            }
        }
        CP_COMMIT();   // one group per chunk (possibly empty near the tail)
    }

    // epilogue: direct fp32 stores (thread owns rows m, m+8; cols 2*(lane&3)+{0,1})
    const int rbase = m0 + warp_m * 64 + (lane >> 2);
    const int cbase = n0 + warp_n * 64 + (lane & 3) * 2;
#pragma unroll
    for (int i = 0; i < 4; i++) {
#pragma unroll
        for (int j = 0; j < 8; j++) {
            float2 v0 = make_float2(acc[i][j][0], acc[i][j][1]);
            float2 v1 = make_float2(acc[i][j][2], acc[i][j][3]);
            size_t r0 = (size_t)(rbase + i * 16) * DOUT + (cbase + j * 8);
            size_t r1 = r0 + 8 * (size_t)DOUT;
            *(float2*)(out + r0) = v0;
            *(float2*)(out + r1) = v1;
        }
    }
}

// ------------------------- launch -------------------------
extern "C" void kernel_launch(void* const* d_in, const int* in_sizes, int n_in,
                              void* d_out, int out_size) {
    (void)in_sizes; (void)n_in; (void)out_size;
    const float* x   = (const float*)d_in[0];
    const float* w   = (const float*)d_in[1];
    const float* hra = (const float*)d_in[2];
    float* out = (float*)d_out;

    k_prep<<<1, 256>>>(hra);
    k_wprep<<<DOUT, 256>>>(w);
    k_xconv<<<8192, 256>>>(x);

    cudaFuncSetAttribute(k_gemm, cudaFuncAttributeMaxDynamicSharedMemorySize, GEMM_SMEM);
    k_gemm<<<(MTOT / 128) * (DOUT / 128), 128, GEMM_SMEM>>>(out);
}